// round 16
// baseline (speedup 1.0000x reference)
#include <cuda_runtime.h>
#include <cuda_fp16.h>
#include <cstdint>

// Problem constants (fixed by the dataset)
#define NCH   12
#define GD    160
#define GH    160
#define GW    160
#define GVOL  (GD * GH * GW)          // 4,096,000 voxels

// Interleaved channel-last fp16 grid: [D*H*W, 12] halfs = 24 B/voxel, 98.3 MB.
// +pad voxels: unconditional x0+1 read at last voxel (weight fx==0) and 64B
// aligned-window over-read. Zero-initialized .bss.
__device__ __align__(16) __half g_grid_h[((size_t)GVOL + 8) * NCH];

// ---------------------------------------------------------------------------
// Pass 1: transpose+convert [C, D, H, W] fp32 -> [D*H*W, C] fp16.
// One thread = FOUR consecutive voxels: 12x LDG.128 (float4 per channel,
// fully coalesced) -> 96 contiguous bytes out = 6x STG.128.
// ---------------------------------------------------------------------------
__global__ void __launch_bounds__(256) convert_cl_kernel(const float* __restrict__ grid) {
    int t = blockIdx.x * blockDim.x + threadIdx.x;
    int v = t * 4;
    if (v >= GVOL) return;

    __half h[4 * NCH];                  // voxel-major: h[v'*12 + c]
#pragma unroll
    for (int c = 0; c < NCH; c++) {
        float4 f = __ldcs(reinterpret_cast<const float4*>(grid + (size_t)c * GVOL + v));
        h[0 * NCH + c] = __float2half(f.x);
        h[1 * NCH + c] = __float2half(f.y);
        h[2 * NCH + c] = __float2half(f.z);
        h[3 * NCH + c] = __float2half(f.w);
    }

    uint4* dst = reinterpret_cast<uint4*>(g_grid_h + (size_t)v * NCH);  // 96B, 16B-aligned
    const uint4* s = reinterpret_cast<const uint4*>(h);
#pragma unroll
    for (int k = 0; k < 6; k++)
        dst[k] = s[k];
}

// ---------------------------------------------------------------------------
// Pass 2: trilinear sample, one thread per point, all 12 channels.
// Corner-pair (48B at 8B alignment) fetched via a 16B-aligned window:
// 3x LDG.128 + 1 predicated LDG.128 (only when the pair straddles, sh==1).
// TWO pairs batched in flight (latency hiding — R13 showed this matters).
// ---------------------------------------------------------------------------
__device__ __forceinline__ float2 u2f2(unsigned u) {
    __half2 h = *reinterpret_cast<__half2*>(&u);
    return __half22float2(h);
}

__global__ void __launch_bounds__(256, 4) trilinear_sample_kernel(
    const float* __restrict__ xyz,
    const float* __restrict__ xyz_min,
    const float* __restrict__ xyz_max,
    float* __restrict__ out,
    int n)
{
    int i = blockIdx.x * blockDim.x + threadIdx.x;
    if (i >= n) return;

    float p0 = __ldcs(xyz + 3 * (size_t)i + 0);
    float p1 = __ldcs(xyz + 3 * (size_t)i + 1);
    float p2 = __ldcs(xyz + 3 * (size_t)i + 2);

    float mn0 = __ldg(xyz_min + 0), mn1 = __ldg(xyz_min + 1), mn2 = __ldg(xyz_min + 2);
    float mx0 = __ldg(xyz_max + 0), mx1 = __ldg(xyz_max + 1), mx2 = __ldg(xyz_max + 2);

    float u0 = (p0 - mn0) / (mx0 - mn0);
    float u1 = (p1 - mn1) / (mx1 - mn1);
    float u2 = (p2 - mn2) / (mx2 - mn2);

    // px indexes W (from u2), py indexes H (from u1), pz indexes D (from u0)
    float px = u2 * (float)(GW - 1);
    float py = u1 * (float)(GH - 1);
    float pz = u0 * (float)(GD - 1);

    float xf = floorf(px), yf = floorf(py), zf = floorf(pz);
    float fx = px - xf,    fy = py - yf,    fz = pz - zf;

    int x0 = min(max((int)xf, 0), GW - 1);
    int y0 = min(max((int)yf, 0), GH - 1);
    int z0 = min(max((int)zf, 0), GD - 1);
    int y1 = min(y0 + 1, GH - 1);
    int z1 = min(z0 + 1, GD - 1);

    float wx0 = 1.0f - fx, wx1 = fx;
    float wy0 = 1.0f - fy, wy1 = fy;
    float wz0 = 1.0f - fz, wz1 = fz;

    float wp[4];
    wp[0] = wz0 * wy0;
    wp[1] = wz0 * wy1;
    wp[2] = wz1 * wy0;
    wp[3] = wz1 * wy1;

    int vidx[4];
    vidx[0] = (z0 * GH + y0) * GW + x0;
    vidx[1] = (z0 * GH + y1) * GW + x0;
    vidx[2] = (z1 * GH + y0) * GW + x0;
    vidx[3] = (z1 * GH + y1) * GW + x0;

    const char* gbase = reinterpret_cast<const char*>(g_grid_h);

    float acc[NCH];
#pragma unroll
    for (int c = 0; c < NCH; c++) acc[c] = 0.0f;

    // Two pairs in flight: 6-8 LDG.128 issued back-to-back, then consume.
#pragma unroll
    for (int pb = 0; pb < 4; pb += 2) {
        uint4 W[8];
        bool  sh[2];
#pragma unroll
        for (int t = 0; t < 2; t++) {
            int B = vidx[pb + t] * 24;           // byte offset; B mod 16 in {0,8}
            const uint4* q = reinterpret_cast<const uint4*>(gbase + (B & ~15));
            sh[t] = (B & 8) != 0;
            W[t * 4 + 0] = __ldg(q + 0);
            W[t * 4 + 1] = __ldg(q + 1);
            W[t * 4 + 2] = __ldg(q + 2);
            W[t * 4 + 3] = make_uint4(0u, 0u, 0u, 0u);
            if (sh[t]) W[t * 4 + 3] = __ldg(q + 3);  // only needed when straddling
        }

#pragma unroll
        for (int t = 0; t < 2; t++) {
            int p = pb + t;
            float w0 = wp[p] * wx0;
            float w1 = wp[p] * wx1;

            unsigned wd[16];
            wd[0]  = W[t*4+0].x; wd[1]  = W[t*4+0].y; wd[2]  = W[t*4+0].z; wd[3]  = W[t*4+0].w;
            wd[4]  = W[t*4+1].x; wd[5]  = W[t*4+1].y; wd[6]  = W[t*4+1].z; wd[7]  = W[t*4+1].w;
            wd[8]  = W[t*4+2].x; wd[9]  = W[t*4+2].y; wd[10] = W[t*4+2].z; wd[11] = W[t*4+2].w;
            wd[12] = W[t*4+3].x; wd[13] = W[t*4+3].y; wd[14] = W[t*4+3].z; wd[15] = W[t*4+3].w;

            // Pair occupies wd[off .. off+11], off = sh ? 2 : 0.
            unsigned u[12];
#pragma unroll
            for (int k = 0; k < 12; k++)
                u[k] = sh[t] ? wd[k + 2] : wd[k];

            // u[0..5] = x0 ch0-11 (half2 each), u[6..11] = x0+1 ch0-11
#pragma unroll
            for (int j = 0; j < 6; j++) {
                float2 a = u2f2(u[j]);
                float2 b = u2f2(u[6 + j]);
                acc[2*j]   = fmaf(w0, a.x, fmaf(w1, b.x, acc[2*j]));
                acc[2*j+1] = fmaf(w0, a.y, fmaf(w1, b.y, acc[2*j+1]));
            }
        }
    }

    // out is [N, 12] row-major; 48B per thread -> 3x float4 streaming stores
    float4* o = reinterpret_cast<float4*>(out + (size_t)i * NCH);
    __stcs(o + 0, make_float4(acc[0], acc[1], acc[2],  acc[3]));
    __stcs(o + 1, make_float4(acc[4], acc[5], acc[6],  acc[7]));
    __stcs(o + 2, make_float4(acc[8], acc[9], acc[10], acc[11]));
}

extern "C" void kernel_launch(void* const* d_in, const int* in_sizes, int n_in,
                              void* d_out, int out_size) {
    const float* xyz     = (const float*)d_in[0];  // [N, 3]
    const float* grid    = (const float*)d_in[1];  // [1, 12, 160, 160, 160]
    const float* xyz_min = (const float*)d_in[2];  // [3]
    const float* xyz_max = (const float*)d_in[3];  // [3]
    float* out = (float*)d_out;                    // [N, 12]

    int n = in_sizes[0] / 3;

    {
        int blocks = (GVOL / 4 + 255) / 256;
        convert_cl_kernel<<<blocks, 256>>>(grid);
    }
    {
        int threads = 256;
        int blocks = (n + threads - 1) / threads;
        trilinear_sample_kernel<<<blocks, threads>>>(xyz, xyz_min, xyz_max, out, n);
    }
}

// round 17
// speedup vs baseline: 1.0903x; 1.0903x over previous
#include <cuda_runtime.h>
#include <cuda_fp16.h>
#include <cstdint>

// Problem constants (fixed by the dataset)
#define NCH   12
#define GD    160
#define GH    160
#define GW    160
#define GVOL  (GD * GH * GW)          // 4,096,000 voxels

// Interleaved channel-last fp16 grid: [D*H*W, 12] halfs = 24 B/voxel, 98.3 MB.
// +pad voxels: unconditional x0+1 read at last voxel (weight fx==0) and 64B
// aligned-window over-read. Zero-initialized .bss.
__device__ __align__(16) __half g_grid_h[((size_t)GVOL + 8) * NCH];

// ---------------------------------------------------------------------------
// Pass 1: transpose+convert [C, D, H, W] fp32 -> [D*H*W, C] fp16.
// Each block handles 512 consecutive voxels (2 per thread). Converted data is
// staged in SMEM, then written as ONE contiguous 12 KB run of STG.128 —
// ideal store wavefronts (direct interleaved stores cost 3x; measured
// 45-52us vs 37-40us for coalesced-store variants).
// ---------------------------------------------------------------------------
__global__ void __launch_bounds__(256) convert_cl_kernel(const float* __restrict__ grid) {
    __shared__ __half sh_tile[512 * NCH];          // 12,288 B

    int t = threadIdx.x;
    int vbase = blockIdx.x * 512;
    int v = vbase + t * 2;                         // 2 consecutive voxels per thread

    __half h[2 * NCH];
#pragma unroll
    for (int c = 0; c < NCH; c++) {
        float2 f = __ldcs(reinterpret_cast<const float2*>(grid + (size_t)c * GVOL + v));
        h[c]       = __float2half(f.x);
        h[NCH + c] = __float2half(f.y);
    }

    // Stage 48B per thread into smem (3x STS.128; minor bank conflicts, cheap).
    {
        uint4* s = reinterpret_cast<uint4*>(sh_tile + t * 2 * NCH);
        const uint4* src = reinterpret_cast<const uint4*>(h);
        s[0] = src[0];
        s[1] = src[1];
        s[2] = src[2];
    }
    __syncthreads();

    // Contiguous copy: 12288 B = 768 uint4; 3 per thread, fully coalesced.
    uint4* dst = reinterpret_cast<uint4*>(g_grid_h + (size_t)vbase * NCH);
    const uint4* s = reinterpret_cast<const uint4*>(sh_tile);
#pragma unroll
    for (int k = 0; k < 3; k++)
        dst[k * 256 + t] = s[k * 256 + t];
}

// ---------------------------------------------------------------------------
// Pass 2: trilinear sample, one thread per point, all 12 channels.
// Corner-pair (48B at 8B alignment) fetched via a 16B-aligned 64B window:
// 4x LDG.128 unconditional (predication measured slower). TWO pairs batched
// in flight for latency hiding. Best-measured config: 108.1us.
// ---------------------------------------------------------------------------
__device__ __forceinline__ float2 u2f2(unsigned u) {
    __half2 h = *reinterpret_cast<__half2*>(&u);
    return __half22float2(h);
}

__global__ void __launch_bounds__(256, 4) trilinear_sample_kernel(
    const float* __restrict__ xyz,
    const float* __restrict__ xyz_min,
    const float* __restrict__ xyz_max,
    float* __restrict__ out,
    int n)
{
    int i = blockIdx.x * blockDim.x + threadIdx.x;
    if (i >= n) return;

    float p0 = __ldcs(xyz + 3 * (size_t)i + 0);
    float p1 = __ldcs(xyz + 3 * (size_t)i + 1);
    float p2 = __ldcs(xyz + 3 * (size_t)i + 2);

    float mn0 = __ldg(xyz_min + 0), mn1 = __ldg(xyz_min + 1), mn2 = __ldg(xyz_min + 2);
    float mx0 = __ldg(xyz_max + 0), mx1 = __ldg(xyz_max + 1), mx2 = __ldg(xyz_max + 2);

    float u0 = (p0 - mn0) / (mx0 - mn0);
    float u1 = (p1 - mn1) / (mx1 - mn1);
    float u2 = (p2 - mn2) / (mx2 - mn2);

    // px indexes W (from u2), py indexes H (from u1), pz indexes D (from u0)
    float px = u2 * (float)(GW - 1);
    float py = u1 * (float)(GH - 1);
    float pz = u0 * (float)(GD - 1);

    float xf = floorf(px), yf = floorf(py), zf = floorf(pz);
    float fx = px - xf,    fy = py - yf,    fz = pz - zf;

    int x0 = min(max((int)xf, 0), GW - 1);
    int y0 = min(max((int)yf, 0), GH - 1);
    int z0 = min(max((int)zf, 0), GD - 1);
    int y1 = min(y0 + 1, GH - 1);
    int z1 = min(z0 + 1, GD - 1);

    float wx0 = 1.0f - fx, wx1 = fx;
    float wy0 = 1.0f - fy, wy1 = fy;
    float wz0 = 1.0f - fz, wz1 = fz;

    float wp[4];
    wp[0] = wz0 * wy0;
    wp[1] = wz0 * wy1;
    wp[2] = wz1 * wy0;
    wp[3] = wz1 * wy1;

    int vidx[4];
    vidx[0] = (z0 * GH + y0) * GW + x0;
    vidx[1] = (z0 * GH + y1) * GW + x0;
    vidx[2] = (z1 * GH + y0) * GW + x0;
    vidx[3] = (z1 * GH + y1) * GW + x0;

    const char* gbase = reinterpret_cast<const char*>(g_grid_h);

    float acc[NCH];
#pragma unroll
    for (int c = 0; c < NCH; c++) acc[c] = 0.0f;

    // Two pairs in flight: 8x LDG.128 issued back-to-back, then consume.
#pragma unroll
    for (int pb = 0; pb < 4; pb += 2) {
        uint4 W[8];
        bool  sh[2];
#pragma unroll
        for (int t = 0; t < 2; t++) {
            int B = vidx[pb + t] * 24;           // byte offset; B mod 16 in {0,8}
            const uint4* q = reinterpret_cast<const uint4*>(gbase + (B & ~15));
            sh[t] = (B & 8) != 0;
            W[t * 4 + 0] = __ldg(q + 0);
            W[t * 4 + 1] = __ldg(q + 1);
            W[t * 4 + 2] = __ldg(q + 2);
            W[t * 4 + 3] = __ldg(q + 3);
        }

#pragma unroll
        for (int t = 0; t < 2; t++) {
            int p = pb + t;
            float w0 = wp[p] * wx0;
            float w1 = wp[p] * wx1;

            unsigned wd[16];
            wd[0]  = W[t*4+0].x; wd[1]  = W[t*4+0].y; wd[2]  = W[t*4+0].z; wd[3]  = W[t*4+0].w;
            wd[4]  = W[t*4+1].x; wd[5]  = W[t*4+1].y; wd[6]  = W[t*4+1].z; wd[7]  = W[t*4+1].w;
            wd[8]  = W[t*4+2].x; wd[9]  = W[t*4+2].y; wd[10] = W[t*4+2].z; wd[11] = W[t*4+2].w;
            wd[12] = W[t*4+3].x; wd[13] = W[t*4+3].y; wd[14] = W[t*4+3].z; wd[15] = W[t*4+3].w;

            // Pair occupies wd[off .. off+11], off = sh ? 2 : 0.
            unsigned u[12];
#pragma unroll
            for (int k = 0; k < 12; k++)
                u[k] = sh[t] ? wd[k + 2] : wd[k];

            // u[0..5] = x0 ch0-11 (half2 each), u[6..11] = x0+1 ch0-11
#pragma unroll
            for (int j = 0; j < 6; j++) {
                float2 a = u2f2(u[j]);
                float2 b = u2f2(u[6 + j]);
                acc[2*j]   = fmaf(w0, a.x, fmaf(w1, b.x, acc[2*j]));
                acc[2*j+1] = fmaf(w0, a.y, fmaf(w1, b.y, acc[2*j+1]));
            }
        }
    }

    // out is [N, 12] row-major; 48B per thread -> 3x float4 streaming stores
    float4* o = reinterpret_cast<float4*>(out + (size_t)i * NCH);
    __stcs(o + 0, make_float4(acc[0], acc[1], acc[2],  acc[3]));
    __stcs(o + 1, make_float4(acc[4], acc[5], acc[6],  acc[7]));
    __stcs(o + 2, make_float4(acc[8], acc[9], acc[10], acc[11]));
}

extern "C" void kernel_launch(void* const* d_in, const int* in_sizes, int n_in,
                              void* d_out, int out_size) {
    const float* xyz     = (const float*)d_in[0];  // [N, 3]
    const float* grid    = (const float*)d_in[1];  // [1, 12, 160, 160, 160]
    const float* xyz_min = (const float*)d_in[2];  // [3]
    const float* xyz_max = (const float*)d_in[3];  // [3]
    float* out = (float*)d_out;                    // [N, 12]

    int n = in_sizes[0] / 3;

    {
        int blocks = GVOL / 512;                   // 8000 exact
        convert_cl_kernel<<<blocks, 256>>>(grid);
    }
    {
        int threads = 256;
        int blocks = (n + threads - 1) / threads;
        trilinear_sample_kernel<<<blocks, threads>>>(xyz, xyz_min, xyz_max, out, n);
    }
}